// round 15
// baseline (speedup 1.0000x reference)
#include <cuda_runtime.h>
#include <cstdint>

#define MAX_NODES 100000
#define EDGE_TB   256
#define NODE_TB   256
#define NODE_GRID 148
#define NODE_PER  3          // 148*256*3 = 113664 >= 100000
#define DEG_SCALE 512.0f
#define INV_SCALE (1.0f / 512.0f)

// Packed accumulator: acc[i].x = 512*deg + C4, acc[i].y = S4.
// |C4| <= deg <= ~90 << 256, so deg and C4 separate exactly via rintf.
struct Scratch {
    float2   acc[MAX_NODES];
    float    part[2];         // [0] pair_loss_sum, [1] n_pairs
    unsigned done;            // finalize ticket (node blocks)
    unsigned tick;            // edge-block completion counter
};
__device__ Scratch g_s;

__device__ __forceinline__ void red_v2(float2* addr, float a, float b) {
    asm volatile("red.global.add.v2.f32 [%0], {%1, %2};"
                 :: "l"(addr), "f"(a), "f"(b)
                 : "memory");
}

__global__ void edge_kernel(const float* __restrict__ pos,
                            const int*   __restrict__ ei,
                            int E) {
    int e = blockIdx.x * blockDim.x + threadIdx.x;
    if (e < E) {
        int s = ei[e];
        int t = ei[E + e];
        float2 ps = __ldg((const float2*)pos + s);
        float2 pt = __ldg((const float2*)pos + t);
        float dx = pt.x - ps.x;
        float dy = pt.y - ps.y;
        float nrm = sqrtf(fmaf(dx, dx, dy * dy));
        float inv = 1.0f / fmaxf(nrm, 1e-8f);
        float u = dx * inv, v = dy * inv;
        // cos(2t) = u^2 - v^2 ; sin(2t) = 2uv ; double-angle again for 4t.
        float a = u * u - v * v;
        float b = 2.0f * u * v;
        float c4 = a * a - b * b;
        float s4 = 2.0f * a * b;
        // 4-theta invariant under d -> -d: identical payload to both endpoints.
        // Degree folded into the x channel as +DEG_SCALE.
        red_v2(&g_s.acc[s], DEG_SCALE + c4, s4);
        red_v2(&g_s.acc[t], DEG_SCALE + c4, s4);
    }
    // Publish this block's REDs: bar.sync (intra-block HB) + ONE cumulative
    // gpu fence + ticket. (Per-thread fences were the R12 disaster.)
    __syncthreads();
    if (threadIdx.x == 0) {
        __threadfence();
        atomicAdd(&g_s.tick, 1u);
    }
}

__global__ __launch_bounds__(NODE_TB, 1)
void node_kernel(int n, unsigned edge_blocks, float* __restrict__ out) {
    // Runs CONCURRENTLY with edge_kernel (forked stream). Wait device-side
    // until every edge block has published, then reduce.
    if (threadIdx.x == 0) {
        while (atomicAdd(&g_s.tick, 0u) < edge_blocks) __nanosleep(256);
        __threadfence();   // acquire: all published REDs now visible
    }
    __syncthreads();

    const int tid    = blockIdx.x * blockDim.x + threadIdx.x;
    const int stride = NODE_GRID * NODE_TB;
    float pl = 0.0f, np = 0.0f;
    #pragma unroll
    for (int r = 0; r < NODE_PER; r++) {
        int i = tid + r * stride;
        if (i < n) {
            float2 acc = g_s.acc[i];
            float k  = rintf(acc.x * INV_SCALE);       // exact degree
            float c4 = fmaf(k, -DEG_SCALE, acc.x);     // C4 = x - 512*k
            float s4 = acc.y;
            // sum_{i<j}(dot^2-dot^4) = (k^2 - C4^2 - S4^2)/16 (incl. 0.5 pair factor)
            pl += (k * k - (c4 * c4 + s4 * s4)) * 0.0625f;
            np += 0.5f * k * (k - 1.0f);
        }
    }

    #pragma unroll
    for (int o = 16; o > 0; o >>= 1) {
        pl += __shfl_down_sync(0xffffffffu, pl, o);
        np += __shfl_down_sync(0xffffffffu, np, o);
    }
    __shared__ float s_pl[NODE_TB / 32];
    __shared__ float s_np[NODE_TB / 32];
    int lane = threadIdx.x & 31;
    int wid  = threadIdx.x >> 5;
    if (lane == 0) { s_pl[wid] = pl; s_np[wid] = np; }
    __syncthreads();
    if (wid == 0) {
        pl = (lane < NODE_TB / 32) ? s_pl[lane] : 0.0f;
        np = (lane < NODE_TB / 32) ? s_np[lane] : 0.0f;
        #pragma unroll
        for (int o = 16; o > 0; o >>= 1) {
            pl += __shfl_down_sync(0xffffffffu, pl, o);
            np += __shfl_down_sync(0xffffffffu, np, o);
        }
        if (lane == 0) {
            atomicAdd(&g_s.part[0], pl);
            atomicAdd(&g_s.part[1], np);
            __threadfence();
            unsigned done = atomicAdd(&g_s.done, 1u);
            if (done == gridDim.x - 1) {
                volatile float* p = g_s.part;
                float a = p[0];
                float b = p[1];
                out[0] = a / fmaxf(b, 1.0f);
            }
        }
    }
}

extern "C" void kernel_launch(void* const* d_in, const int* in_sizes, int n_in,
                              void* d_out, int out_size) {
    const float* pos = (const float*)d_in[0];
    const int*   ei  = (const int*)d_in[2];
    int N = in_sizes[0] / 2;      // node_positions: (1, N, 2)
    int E = in_sizes[2] / 2;      // edge_index: (2, E)

    // One-time setup on the first (uncaptured, correctness) call.
    static cudaStream_t s2 = nullptr;
    static cudaEvent_t  evFork = nullptr, evJoin = nullptr;
    if (s2 == nullptr) {
        cudaStreamCreateWithFlags(&s2, cudaStreamNonBlocking);
        cudaEventCreateWithFlags(&evFork, cudaEventDisableTiming);
        cudaEventCreateWithFlags(&evJoin, cudaEventDisableTiming);
        cudaFuncSetAttribute(edge_kernel,
                             cudaFuncAttributePreferredSharedMemoryCarveout, 0);
    }

    void* scratch_ptr = nullptr;
    cudaGetSymbolAddress(&scratch_ptr, g_s);
    cudaMemsetAsync(scratch_ptr, 0, sizeof(Scratch), 0);   // clears acc+part+done+tick

    unsigned edge_blocks = (unsigned)((E + EDGE_TB - 1) / EDGE_TB);

    // Fork: node_kernel runs on s2 concurrently with edge_kernel on stream 0;
    // both depend on the memset. Join s2 back so the graph has one exit.
    cudaEventRecord(evFork, 0);
    cudaStreamWaitEvent(s2, evFork, 0);

    edge_kernel<<<edge_blocks, EDGE_TB, 0, 0>>>(pos, ei, E);
    node_kernel<<<NODE_GRID, NODE_TB, 0, s2>>>(N, edge_blocks, (float*)d_out);

    cudaEventRecord(evJoin, s2);
    cudaStreamWaitEvent(0, evJoin, 0);
}

// round 16
// speedup vs baseline: 1.1478x; 1.1478x over previous
#include <cuda_runtime.h>
#include <cstdint>

#define MAX_NODES 100000
#define EDGE_TB   512
#define NODE_TB   1024
#define NODE_GRID 148   // 148*1024 = 151552 >= 100000, single wave, 1 node/thread
#define DEG_SCALE 512.0f
#define INV_SCALE (1.0f / 512.0f)

// Packed accumulator: acc[i].x = 512*deg + C4, acc[i].y = S4.
// |C4| <= deg <= ~90 << 256, so deg and C4 separate exactly via rintf.
struct Scratch {
    float2   acc[MAX_NODES];
    float    part[2];         // [0] pair_loss_sum, [1] n_pairs
    unsigned done;
};
__device__ Scratch g_s;

__device__ __forceinline__ void red_v2(float2* addr, float a, float b) {
    asm volatile("red.global.add.v2.f32 [%0], {%1, %2};"
                 :: "l"(addr), "f"(a), "f"(b)
                 : "memory");
}

__global__ __launch_bounds__(EDGE_TB)
void edge_kernel(const float* __restrict__ pos,
                 const int*   __restrict__ ei,
                 int E) {
    int e = blockIdx.x * EDGE_TB + threadIdx.x;
    if (e >= E) return;
    int s = ei[e];
    int t = ei[E + e];
    float2 ps = __ldg((const float2*)pos + s);
    float2 pt = __ldg((const float2*)pos + t);
    float dx = pt.x - ps.x;
    float dy = pt.y - ps.y;
    float nrm = sqrtf(fmaf(dx, dx, dy * dy));
    float inv = 1.0f / fmaxf(nrm, 1e-8f);
    float u = dx * inv, v = dy * inv;
    // cos(2t) = u^2 - v^2 ; sin(2t) = 2uv ; double-angle again for 4t.
    float a = u * u - v * v;
    float b = 2.0f * u * v;
    float c4 = a * a - b * b;
    float s4 = 2.0f * a * b;
    // 4-theta terms invariant under d -> -d: identical payload to both endpoints.
    // Degree folded into the x channel as +DEG_SCALE.
    red_v2(&g_s.acc[s], DEG_SCALE + c4, s4);
    red_v2(&g_s.acc[t], DEG_SCALE + c4, s4);
}

__global__ __launch_bounds__(NODE_TB, 1)
void node_kernel(int n, float* __restrict__ out) {
    const int i = blockIdx.x * blockDim.x + threadIdx.x;

    float pl = 0.0f, np = 0.0f;
    if (i < n) {
        float2 acc = g_s.acc[i];
        float k  = rintf(acc.x * INV_SCALE);       // exact degree
        float c4 = fmaf(k, -DEG_SCALE, acc.x);     // C4 = x - 512*k
        float s4 = acc.y;
        // sum_{i<j}(dot^2 - dot^4) = (k^2 - C4^2 - S4^2)/16 (incl. 0.5 pair factor)
        pl = (k * k - (c4 * c4 + s4 * s4)) * 0.0625f;
        np = 0.5f * k * (k - 1.0f);
    }

    #pragma unroll
    for (int o = 16; o > 0; o >>= 1) {
        pl += __shfl_down_sync(0xffffffffu, pl, o);
        np += __shfl_down_sync(0xffffffffu, np, o);
    }
    __shared__ float s_pl[32];
    __shared__ float s_np[32];
    int lane = threadIdx.x & 31;
    int wid  = threadIdx.x >> 5;
    if (lane == 0) { s_pl[wid] = pl; s_np[wid] = np; }
    __syncthreads();
    if (wid == 0) {
        pl = s_pl[lane];
        np = s_np[lane];
        #pragma unroll
        for (int o = 16; o > 0; o >>= 1) {
            pl += __shfl_down_sync(0xffffffffu, pl, o);
            np += __shfl_down_sync(0xffffffffu, np, o);
        }
        if (lane == 0) {
            atomicAdd(&g_s.part[0], pl);
            atomicAdd(&g_s.part[1], np);
            __threadfence();
            unsigned done = atomicAdd(&g_s.done, 1u);
            if (done == gridDim.x - 1) {
                volatile float* p = g_s.part;
                float a = p[0];
                float b = p[1];
                out[0] = a / fmaxf(b, 1.0f);
            }
        }
    }
}

extern "C" void kernel_launch(void* const* d_in, const int* in_sizes, int n_in,
                              void* d_out, int out_size) {
    const float* pos = (const float*)d_in[0];
    const int*   ei  = (const int*)d_in[2];
    int N = in_sizes[0] / 2;      // node_positions: (1, N, 2)
    int E = in_sizes[2] / 2;      // edge_index: (2, E)

    static bool configured = false;
    if (!configured) {
        cudaFuncSetAttribute(edge_kernel,
                             cudaFuncAttributePreferredSharedMemoryCarveout, 0);
        configured = true;
    }

    void* scratch_ptr = nullptr;
    cudaGetSymbolAddress(&scratch_ptr, g_s);
    cudaMemsetAsync(scratch_ptr, 0, sizeof(Scratch));  // captured memset node

    edge_kernel<<<(E + EDGE_TB - 1) / EDGE_TB, EDGE_TB>>>(pos, ei, E);
    node_kernel<<<NODE_GRID, NODE_TB>>>(N, (float*)d_out);
}